// round 5
// baseline (speedup 1.0000x reference)
#include <cuda_runtime.h>
#include <math.h>

#define BB 4
#define LL 8192
#define HH 128
#define PP 64
// pc = c*64 + p : first 64 rows = real channel, next 64 = imag channel
// g_buf layout: [(b*128 + pc) * LL + l]
__device__ float g_buf[BB * 2 * PP * LL];   // 16 MB scratch (Bu, then x2 in-place)

// padded smem index: 1 pad float per 32 -> chunk t starts at t*33, bank(t,i)=(t+i)%32
#define IDX(i) ((i) + ((i) >> 5))
#define LLP (LL + (LL >> 5))   // 8448

// ---------------------------------------------------------------------------
// K1: Bu = u @ [B_real ; B_imag]^T
// grid (L/128, B), 256 threads, out tile 128(l) x 128(pc), K = H = 128
// ---------------------------------------------------------------------------
__global__ __launch_bounds__(256) void k_bu(const float* __restrict__ u,
                                            const float* __restrict__ Br,
                                            const float* __restrict__ Bi)
{
    extern __shared__ float sm[];
    float* Ask = sm;               // [h][l]  stride 132
    float* Wsk = sm + 128 * 132;   // [h][pc] stride 132
    const int b = blockIdx.y, l0 = blockIdx.x * 128, tid = threadIdx.x;

    const float* ub = u + ((size_t)b * LL + l0) * HH;
    #pragma unroll 4
    for (int idx = tid; idx < 128 * 128; idx += 256) {
        int l = idx >> 7, h = idx & 127;
        Ask[h * 132 + l] = ub[l * HH + h];
    }
    #pragma unroll 4
    for (int idx = tid; idx < 2 * 64 * 128; idx += 256) {
        int h = idx & 127, p = (idx >> 7) & 63, c = idx >> 13;
        float v = c ? Bi[p * HH + h] : Br[p * HH + h];
        Wsk[h * 132 + c * 64 + p] = v;
    }
    __syncthreads();

    const int tx = tid & 15, ty = tid >> 4;   // tx -> l, ty -> pc
    float acc[8][8];
    #pragma unroll
    for (int i = 0; i < 8; i++)
        #pragma unroll
        for (int j = 0; j < 8; j++) acc[i][j] = 0.f;

    #pragma unroll 4
    for (int k = 0; k < 128; k++) {
        float4 a0 = *(const float4*)(Ask + k * 132 + (tx << 2));
        float4 a1 = *(const float4*)(Ask + k * 132 + 64 + (tx << 2));
        float4 w0 = *(const float4*)(Wsk + k * 132 + (ty << 2));
        float4 w1 = *(const float4*)(Wsk + k * 132 + 64 + (ty << 2));
        float av[8] = {a0.x, a0.y, a0.z, a0.w, a1.x, a1.y, a1.z, a1.w};
        float wv[8] = {w0.x, w0.y, w0.z, w0.w, w1.x, w1.y, w1.z, w1.w};
        #pragma unroll
        for (int i = 0; i < 8; i++)
            #pragma unroll
            for (int j = 0; j < 8; j++)
                acc[i][j] = fmaf(av[i], wv[j], acc[i][j]);
    }

    #pragma unroll
    for (int pj = 0; pj < 8; pj++) {
        int pc = (pj < 4) ? (ty * 4 + pj) : (64 + ty * 4 + pj - 4);
        float* dst = g_buf + ((size_t)(b * 128 + pc)) * LL + l0;
        *(float4*)(dst + (tx << 2))      = make_float4(acc[0][pj], acc[1][pj], acc[2][pj], acc[3][pj]);
        *(float4*)(dst + 64 + (tx << 2)) = make_float4(acc[4][pj], acc[5][pj], acc[6][pj], acc[7][pj]);
    }
}

// ---------------------------------------------------------------------------
// K2: per-(b,p) linear recurrence over L=8192 via blocked scan.
// One block per (b,p). 256 threads x 32 steps.
// smem uses IDX padding -> conflict-free chunk access in both compute passes.
// Chunk-state scan: 5 intra-warp shuffle steps + 1 barrier + serial warp prefix.
// ---------------------------------------------------------------------------
__global__ __launch_bounds__(256) void k_scan(const float* __restrict__ Ad,
                                              const float* __restrict__ stp_in)
{
    extern __shared__ float sm[];
    float* sre = sm;                  // [LLP]
    float* sim = sm + LLP;            // [LLP]
    float* sA  = sm + 2 * LLP;        // [8 warps * 4]
    float* sS  = sm + 2 * LLP + 32;   // [8 warps * 4]

    const int p = blockIdx.x, b = blockIdx.y, t = threadIdx.x;
    const int lane = t & 31, w = t >> 5;
    const size_t base_re = ((size_t)(b * 128 + p)) * LL;
    const size_t base_im = ((size_t)(b * 128 + 64 + p)) * LL;

    // stage Bu rows into padded smem: global coalesced, smem conflict-free
    {
        const float* gr = g_buf + base_re;
        const float* gi = g_buf + base_im;
        #pragma unroll 8
        for (int idx = t; idx < LL; idx += 256) {
            sre[IDX(idx)] = gr[idx];
            sim[IDX(idx)] = gi[idx];
        }
    }

    const float A   = fmaxf(Ad[p], 0.f);
    const float stp = 1.f / (1.f + expf(-stp_in[p]));
    const float s2  = stp * stp;
    const float sch = 1.f / (1.f + s2 * A);
    const float m11 = 1.f - s2 * A * sch;
    const float m12 = -stp * A * sch;
    const float m21 = stp * sch;
    const float m22 = sch;
    const float c1  = m11 * stp;
    const float c2  = m21 * stp;
    __syncthreads();

    // pass 1: local scan of this thread's 32-step chunk from zero state
    const int lb = t * 33;   // physical base of chunk t (IDX(t*32))
    float x1r = 0.f, x2r = 0.f, x1i = 0.f, x2i = 0.f;
    #pragma unroll
    for (int i = 0; i < 32; i++) {
        float br = sre[lb + i], bi = sim[lb + i];
        float n1r = fmaf(m11, x1r, fmaf(m12, x2r, c1 * br));
        float n2r = fmaf(m21, x1r, fmaf(m22, x2r, c2 * br));
        float n1i = fmaf(m11, x1i, fmaf(m12, x2i, c1 * bi));
        float n2i = fmaf(m21, x1i, fmaf(m22, x2i, c2 * bi));
        x1r = n1r; x2r = n2r; x1i = n1i; x2i = n2i;
    }
    // chunk matrix = M^32 by repeated squaring (identical on every thread)
    float a11 = m11, a12 = m12, a21 = m21, a22 = m22;
    #pragma unroll
    for (int q = 0; q < 5; q++) {
        float t11 = a11 * a11 + a12 * a21;
        float t12 = a11 * a12 + a12 * a22;
        float t21 = a21 * a11 + a22 * a21;
        float t22 = a21 * a12 + a22 * a22;
        a11 = t11; a12 = t12; a21 = t21; a22 = t22;
    }

    // intra-warp inclusive scan over chunk states (no barriers)
    #pragma unroll
    for (int d = 1; d < 32; d <<= 1) {
        float pa11 = __shfl_up_sync(0xffffffffu, a11, d);
        float pa12 = __shfl_up_sync(0xffffffffu, a12, d);
        float pa21 = __shfl_up_sync(0xffffffffu, a21, d);
        float pa22 = __shfl_up_sync(0xffffffffu, a22, d);
        float p1r  = __shfl_up_sync(0xffffffffu, x1r, d);
        float p2r  = __shfl_up_sync(0xffffffffu, x2r, d);
        float p1i  = __shfl_up_sync(0xffffffffu, x1i, d);
        float p2i  = __shfl_up_sync(0xffffffffu, x2i, d);
        if (lane >= d) {
            float n1r = a11*p1r + a12*p2r + x1r;
            float n2r = a21*p1r + a22*p2r + x2r;
            float n1i = a11*p1i + a12*p2i + x1i;
            float n2i = a21*p1i + a22*p2i + x2i;
            float na11 = a11*pa11 + a12*pa21;
            float na12 = a11*pa12 + a12*pa22;
            float na21 = a21*pa11 + a22*pa21;
            float na22 = a21*pa12 + a22*pa22;
            x1r=n1r; x2r=n2r; x1i=n1i; x2i=n2i;
            a11=na11; a12=na12; a21=na21; a22=na22;
        }
    }

    // lane 31 publishes warp aggregate
    if (lane == 31) {
        sA[w*4+0]=a11; sA[w*4+1]=a12; sA[w*4+2]=a21; sA[w*4+3]=a22;
        sS[w*4+0]=x1r; sS[w*4+1]=x2r; sS[w*4+2]=x1i; sS[w*4+3]=x2i;
    }
    __syncthreads();

    // state entering this warp (b-part only; uniform within warp)
    float pw1r = 0.f, pw2r = 0.f, pw1i = 0.f, pw2i = 0.f;
    for (int j = 0; j < w; j++) {
        float ja11=sA[j*4+0], ja12=sA[j*4+1], ja21=sA[j*4+2], ja22=sA[j*4+3];
        float js1r=sS[j*4+0], js2r=sS[j*4+1], js1i=sS[j*4+2], js2i=sS[j*4+3];
        float n1r = ja11*pw1r + ja12*pw2r + js1r;
        float n2r = ja21*pw1r + ja22*pw2r + js2r;
        float n1i = ja11*pw1i + ja12*pw2i + js1i;
        float n2i = ja21*pw1i + ja22*pw2i + js2i;
        pw1r=n1r; pw2r=n2r; pw1i=n1i; pw2i=n2i;
    }

    // exclusive per-thread entering state
    float qa11 = __shfl_up_sync(0xffffffffu, a11, 1);
    float qa12 = __shfl_up_sync(0xffffffffu, a12, 1);
    float qa21 = __shfl_up_sync(0xffffffffu, a21, 1);
    float qa22 = __shfl_up_sync(0xffffffffu, a22, 1);
    float q1r  = __shfl_up_sync(0xffffffffu, x1r, 1);
    float q2r  = __shfl_up_sync(0xffffffffu, x2r, 1);
    float q1i  = __shfl_up_sync(0xffffffffu, x1i, 1);
    float q2i  = __shfl_up_sync(0xffffffffu, x2i, 1);

    float i1r, i2r, i1i, i2i;
    if (lane == 0) {
        i1r = pw1r; i2r = pw2r; i1i = pw1i; i2i = pw2i;
    } else {
        i1r = qa11*pw1r + qa12*pw2r + q1r;
        i2r = qa21*pw1r + qa22*pw2r + q2r;
        i1i = qa11*pw1i + qa12*pw2i + q1i;
        i2i = qa21*pw1i + qa22*pw2i + q2i;
    }

    // pass 2: replay with true incoming state, write x2 over Bu in smem
    x1r = i1r; x2r = i2r; x1i = i1i; x2i = i2i;
    #pragma unroll
    for (int i = 0; i < 32; i++) {
        float br = sre[lb + i], bi = sim[lb + i];
        float n1r = fmaf(m11, x1r, fmaf(m12, x2r, c1 * br));
        float n2r = fmaf(m21, x1r, fmaf(m22, x2r, c2 * br));
        float n1i = fmaf(m11, x1i, fmaf(m12, x2i, c1 * bi));
        float n2i = fmaf(m21, x1i, fmaf(m22, x2i, c2 * bi));
        x1r = n1r; x2r = n2r; x1i = n1i; x2i = n2i;
        sre[lb + i] = x2r;
        sim[lb + i] = x2i;
    }
    __syncthreads();

    {
        float* gr = g_buf + base_re;
        float* gi = g_buf + base_im;
        #pragma unroll 8
        for (int idx = t; idx < LL; idx += 256) {
            gr[idx] = sre[IDX(idx)];
            gi[idx] = sim[IDX(idx)];
        }
    }
}

// ---------------------------------------------------------------------------
// K3: y = x2cat @ [C_real^T ; -C_imag^T] + u * D
// grid (L/128, B), out tile 128(l) x 128(h), K = 2P = 128
// ---------------------------------------------------------------------------
__global__ __launch_bounds__(256) void k_out(const float* __restrict__ u,
                                             const float* __restrict__ Cr,
                                             const float* __restrict__ Ci,
                                             const float* __restrict__ Dv,
                                             float* __restrict__ out)
{
    extern __shared__ float sm[];
    float* Ask = sm;               // [pc][l] stride 128 (matches g_buf layout)
    float* Wsk = sm + 128 * 128;   // [pc][h] stride 132
    const int b = blockIdx.y, l0 = blockIdx.x * 128, tid = threadIdx.x;

    #pragma unroll 4
    for (int idx = tid; idx < 128 * 32; idx += 256) {
        int pc = idx >> 5, lq = idx & 31;   // float4 granularity over l
        const float4* src = (const float4*)(g_buf + ((size_t)(b * 128 + pc)) * LL + l0);
        ((float4*)(Ask + pc * 128))[lq] = src[lq];
    }
    #pragma unroll 4
    for (int idx = tid; idx < 128 * 64; idx += 256) {
        int h = idx >> 6, p = idx & 63;
        Wsk[p * 132 + h]        = Cr[h * 64 + p];
        Wsk[(64 + p) * 132 + h] = -Ci[h * 64 + p];
    }
    __syncthreads();

    const int tx = tid & 15, ty = tid >> 4;   // tx -> h, ty -> l
    float acc[8][8];   // [l-idx][h-idx]
    #pragma unroll
    for (int i = 0; i < 8; i++)
        #pragma unroll
        for (int j = 0; j < 8; j++) acc[i][j] = 0.f;

    #pragma unroll 4
    for (int k = 0; k < 128; k++) {
        float4 a0 = *(const float4*)(Ask + k * 128 + (ty << 2));
        float4 a1 = *(const float4*)(Ask + k * 128 + 64 + (ty << 2));
        float4 w0 = *(const float4*)(Wsk + k * 132 + (tx << 2));
        float4 w1 = *(const float4*)(Wsk + k * 132 + 64 + (tx << 2));
        float av[8] = {a0.x, a0.y, a0.z, a0.w, a1.x, a1.y, a1.z, a1.w};
        float wv[8] = {w0.x, w0.y, w0.z, w0.w, w1.x, w1.y, w1.z, w1.w};
        #pragma unroll
        for (int i = 0; i < 8; i++)
            #pragma unroll
            for (int j = 0; j < 8; j++)
                acc[i][j] = fmaf(av[i], wv[j], acc[i][j]);
    }

    float d0[4], d1[4];
    #pragma unroll
    for (int j = 0; j < 4; j++) {
        d0[j] = Dv[tx * 4 + j];
        d1[j] = Dv[64 + tx * 4 + j];
    }

    #pragma unroll
    for (int li = 0; li < 8; li++) {
        int l = (li < 4) ? (ty * 4 + li) : (64 + ty * 4 + li - 4);
        const float* urow = u + ((size_t)b * LL + l0 + l) * HH;
        float*       orow = out + ((size_t)b * LL + l0 + l) * HH;
        float4 u0 = *(const float4*)(urow + (tx << 2));
        float4 u1 = *(const float4*)(urow + 64 + (tx << 2));
        float4 o0, o1;
        o0.x = fmaf(u0.x, d0[0], acc[li][0]);
        o0.y = fmaf(u0.y, d0[1], acc[li][1]);
        o0.z = fmaf(u0.z, d0[2], acc[li][2]);
        o0.w = fmaf(u0.w, d0[3], acc[li][3]);
        o1.x = fmaf(u1.x, d1[0], acc[li][4]);
        o1.y = fmaf(u1.y, d1[1], acc[li][5]);
        o1.z = fmaf(u1.z, d1[2], acc[li][6]);
        o1.w = fmaf(u1.w, d1[3], acc[li][7]);
        *(float4*)(orow + (tx << 2))      = o0;
        *(float4*)(orow + 64 + (tx << 2)) = o1;
    }
}

// ---------------------------------------------------------------------------
extern "C" void kernel_launch(void* const* d_in, const int* in_sizes, int n_in,
                              void* d_out, int out_size)
{
    const float* u  = (const float*)d_in[0];   // (B,L,H)
    const float* Ad = (const float*)d_in[1];   // (P)
    const float* Br = (const float*)d_in[2];   // (P,H)
    const float* Bi = (const float*)d_in[3];   // (P,H)
    const float* Cr = (const float*)d_in[4];   // (H,P)
    const float* Ci = (const float*)d_in[5];   // (H,P)
    const float* Dv = (const float*)d_in[6];   // (H)
    const float* st = (const float*)d_in[7];   // (P)
    float* out = (float*)d_out;                // (B,L,H)

    const int smem_bu   = 2 * 128 * 132 * (int)sizeof(float);            // 135168
    const int smem_scan = (2 * LLP + 64) * (int)sizeof(float);           // 67840
    const int smem_out  = (128 * 128 + 128 * 132) * (int)sizeof(float);  // 133120

    // Idempotent, cheap, capture-legal: call every time (no static guards).
    cudaFuncSetAttribute(k_bu,   cudaFuncAttributeMaxDynamicSharedMemorySize, smem_bu);
    cudaFuncSetAttribute(k_scan, cudaFuncAttributeMaxDynamicSharedMemorySize, smem_scan);
    cudaFuncSetAttribute(k_out,  cudaFuncAttributeMaxDynamicSharedMemorySize, smem_out);

    k_bu  <<<dim3(LL / 128, BB), 256, smem_bu  >>>(u, Br, Bi);
    k_scan<<<dim3(PP,       BB), 256, smem_scan>>>(Ad, st);
    k_out <<<dim3(LL / 128, BB), 256, smem_out >>>(u, Cr, Ci, Dv, out);
}

// round 8
// speedup vs baseline: 1.0778x; 1.0778x over previous
#include <cuda_runtime.h>
#include <math.h>

#define BB 4
#define LL 8192
#define HH 128
#define PP 64
// pc = c*64 + p : first 64 rows = real channel, next 64 = imag channel
// g_buf layout: [(b*128 + pc) * LL + l]
__device__ float g_buf[BB * 2 * PP * LL];   // 16 MB scratch (Bu, then x2 in-place)

// padded smem index for scan: 1 pad float per 32 -> bank(t,i)=(t+i)%32
#define IDX(i) ((i) + ((i) >> 5))
#define LLP (LL + (LL >> 5))   // 8448

// ---------------------------------------------------------------------------
// K1: Bu = u @ [B_real ; B_imag]^T
// grid (L/128, B), 512 threads, out tile 128(l) x 128(pc), K = H = 128
// Register tile 8(l) x 4(pc) -> 16 warps/block, 4 warps/SMSP for latency hiding.
// ---------------------------------------------------------------------------
__global__ __launch_bounds__(512) void k_bu(const float* __restrict__ u,
                                            const float* __restrict__ Br,
                                            const float* __restrict__ Bi)
{
    extern __shared__ float sm[];
    float* Ask = sm;               // [h][l]  stride 132
    float* Wsk = sm + 128 * 132;   // [h][pc] stride 132
    const int b = blockIdx.y, l0 = blockIdx.x * 128, tid = threadIdx.x;

    const float* ub = u + ((size_t)b * LL + l0) * HH;
    #pragma unroll 4
    for (int idx = tid; idx < 128 * 128; idx += 512) {
        int l = idx >> 7, h = idx & 127;
        Ask[h * 132 + l] = ub[l * HH + h];
    }
    #pragma unroll 4
    for (int idx = tid; idx < 2 * 64 * 128; idx += 512) {
        int h = idx & 127, p = (idx >> 7) & 63, c = idx >> 13;
        float v = c ? Bi[p * HH + h] : Br[p * HH + h];
        Wsk[h * 132 + c * 64 + p] = v;
    }
    __syncthreads();

    const int tx = tid & 15, ty = tid >> 4;   // tx -> l (8), ty(0..31) -> pc (4)
    float acc[8][4];
    #pragma unroll
    for (int i = 0; i < 8; i++)
        #pragma unroll
        for (int j = 0; j < 4; j++) acc[i][j] = 0.f;

    #pragma unroll 4
    for (int k = 0; k < 128; k++) {
        float4 a0 = *(const float4*)(Ask + k * 132 + (tx << 2));
        float4 a1 = *(const float4*)(Ask + k * 132 + 64 + (tx << 2));
        float4 w0 = *(const float4*)(Wsk + k * 132 + (ty << 2));
        float av[8] = {a0.x, a0.y, a0.z, a0.w, a1.x, a1.y, a1.z, a1.w};
        float wv[4] = {w0.x, w0.y, w0.z, w0.w};
        #pragma unroll
        for (int i = 0; i < 8; i++)
            #pragma unroll
            for (int j = 0; j < 4; j++)
                acc[i][j] = fmaf(av[i], wv[j], acc[i][j]);
    }

    #pragma unroll
    for (int j = 0; j < 4; j++) {
        int pc = ty * 4 + j;   // 0..127 covers real+imag channels
        float* dst = g_buf + ((size_t)(b * 128 + pc)) * LL + l0;
        *(float4*)(dst + (tx << 2))      = make_float4(acc[0][j], acc[1][j], acc[2][j], acc[3][j]);
        *(float4*)(dst + 64 + (tx << 2)) = make_float4(acc[4][j], acc[5][j], acc[6][j], acc[7][j]);
    }
}

// ---------------------------------------------------------------------------
// K2: per-(b,p) linear recurrence over L=8192 via blocked scan.
// One block per (b,p). 256 threads x 32 steps. IDX-padded smem (conflict-free).
// Chunk scan: 5 shuffle steps + 1 barrier + serial warp prefix.
// ---------------------------------------------------------------------------
__global__ __launch_bounds__(256) void k_scan(const float* __restrict__ Ad,
                                              const float* __restrict__ stp_in)
{
    extern __shared__ float sm[];
    float* sre = sm;                  // [LLP]
    float* sim = sm + LLP;            // [LLP]
    float* sA  = sm + 2 * LLP;        // [8 warps * 4]
    float* sS  = sm + 2 * LLP + 32;   // [8 warps * 4]

    const int p = blockIdx.x, b = blockIdx.y, t = threadIdx.x;
    const int lane = t & 31, w = t >> 5;
    const size_t base_re = ((size_t)(b * 128 + p)) * LL;
    const size_t base_im = ((size_t)(b * 128 + 64 + p)) * LL;

    {
        const float* gr = g_buf + base_re;
        const float* gi = g_buf + base_im;
        #pragma unroll 8
        for (int idx = t; idx < LL; idx += 256) {
            sre[IDX(idx)] = gr[idx];
            sim[IDX(idx)] = gi[idx];
        }
    }

    const float A   = fmaxf(Ad[p], 0.f);
    const float stp = 1.f / (1.f + expf(-stp_in[p]));
    const float s2  = stp * stp;
    const float sch = 1.f / (1.f + s2 * A);
    const float m11 = 1.f - s2 * A * sch;
    const float m12 = -stp * A * sch;
    const float m21 = stp * sch;
    const float m22 = sch;
    const float c1  = m11 * stp;
    const float c2  = m21 * stp;
    __syncthreads();

    const int lb = t * 33;   // physical base of chunk t
    float x1r = 0.f, x2r = 0.f, x1i = 0.f, x2i = 0.f;
    #pragma unroll
    for (int i = 0; i < 32; i++) {
        float br = sre[lb + i], bi = sim[lb + i];
        float n1r = fmaf(m11, x1r, fmaf(m12, x2r, c1 * br));
        float n2r = fmaf(m21, x1r, fmaf(m22, x2r, c2 * br));
        float n1i = fmaf(m11, x1i, fmaf(m12, x2i, c1 * bi));
        float n2i = fmaf(m21, x1i, fmaf(m22, x2i, c2 * bi));
        x1r = n1r; x2r = n2r; x1i = n1i; x2i = n2i;
    }
    float a11 = m11, a12 = m12, a21 = m21, a22 = m22;
    #pragma unroll
    for (int q = 0; q < 5; q++) {
        float t11 = a11 * a11 + a12 * a21;
        float t12 = a11 * a12 + a12 * a22;
        float t21 = a21 * a11 + a22 * a21;
        float t22 = a21 * a12 + a22 * a22;
        a11 = t11; a12 = t12; a21 = t21; a22 = t22;
    }

    #pragma unroll
    for (int d = 1; d < 32; d <<= 1) {
        float pa11 = __shfl_up_sync(0xffffffffu, a11, d);
        float pa12 = __shfl_up_sync(0xffffffffu, a12, d);
        float pa21 = __shfl_up_sync(0xffffffffu, a21, d);
        float pa22 = __shfl_up_sync(0xffffffffu, a22, d);
        float p1r  = __shfl_up_sync(0xffffffffu, x1r, d);
        float p2r  = __shfl_up_sync(0xffffffffu, x2r, d);
        float p1i  = __shfl_up_sync(0xffffffffu, x1i, d);
        float p2i  = __shfl_up_sync(0xffffffffu, x2i, d);
        if (lane >= d) {
            float n1r = a11*p1r + a12*p2r + x1r;
            float n2r = a21*p1r + a22*p2r + x2r;
            float n1i = a11*p1i + a12*p2i + x1i;
            float n2i = a21*p1i + a22*p2i + x2i;
            float na11 = a11*pa11 + a12*pa21;
            float na12 = a11*pa12 + a12*pa22;
            float na21 = a21*pa11 + a22*pa21;
            float na22 = a21*pa12 + a22*pa22;
            x1r=n1r; x2r=n2r; x1i=n1i; x2i=n2i;
            a11=na11; a12=na12; a21=na21; a22=na22;
        }
    }

    if (lane == 31) {
        sA[w*4+0]=a11; sA[w*4+1]=a12; sA[w*4+2]=a21; sA[w*4+3]=a22;
        sS[w*4+0]=x1r; sS[w*4+1]=x2r; sS[w*4+2]=x1i; sS[w*4+3]=x2i;
    }
    __syncthreads();

    float pw1r = 0.f, pw2r = 0.f, pw1i = 0.f, pw2i = 0.f;
    for (int j = 0; j < w; j++) {
        float ja11=sA[j*4+0], ja12=sA[j*4+1], ja21=sA[j*4+2], ja22=sA[j*4+3];
        float js1r=sS[j*4+0], js2r=sS[j*4+1], js1i=sS[j*4+2], js2i=sS[j*4+3];
        float n1r = ja11*pw1r + ja12*pw2r + js1r;
        float n2r = ja21*pw1r + ja22*pw2r + js2r;
        float n1i = ja11*pw1i + ja12*pw2i + js1i;
        float n2i = ja21*pw1i + ja22*pw2i + js2i;
        pw1r=n1r; pw2r=n2r; pw1i=n1i; pw2i=n2i;
    }

    float qa11 = __shfl_up_sync(0xffffffffu, a11, 1);
    float qa12 = __shfl_up_sync(0xffffffffu, a12, 1);
    float qa21 = __shfl_up_sync(0xffffffffu, a21, 1);
    float qa22 = __shfl_up_sync(0xffffffffu, a22, 1);
    float q1r  = __shfl_up_sync(0xffffffffu, x1r, 1);
    float q2r  = __shfl_up_sync(0xffffffffu, x2r, 1);
    float q1i  = __shfl_up_sync(0xffffffffu, x1i, 1);
    float q2i  = __shfl_up_sync(0xffffffffu, x2i, 1);

    float i1r, i2r, i1i, i2i;
    if (lane == 0) {
        i1r = pw1r; i2r = pw2r; i1i = pw1i; i2i = pw2i;
    } else {
        i1r = qa11*pw1r + qa12*pw2r + q1r;
        i2r = qa21*pw1r + qa22*pw2r + q2r;
        i1i = qa11*pw1i + qa12*pw2i + q1i;
        i2i = qa21*pw1i + qa22*pw2i + q2i;
    }

    x1r = i1r; x2r = i2r; x1i = i1i; x2i = i2i;
    #pragma unroll
    for (int i = 0; i < 32; i++) {
        float br = sre[lb + i], bi = sim[lb + i];
        float n1r = fmaf(m11, x1r, fmaf(m12, x2r, c1 * br));
        float n2r = fmaf(m21, x1r, fmaf(m22, x2r, c2 * br));
        float n1i = fmaf(m11, x1i, fmaf(m12, x2i, c1 * bi));
        float n2i = fmaf(m21, x1i, fmaf(m22, x2i, c2 * bi));
        x1r = n1r; x2r = n2r; x1i = n1i; x2i = n2i;
        sre[lb + i] = x2r;
        sim[lb + i] = x2i;
    }
    __syncthreads();

    {
        float* gr = g_buf + base_re;
        float* gi = g_buf + base_im;
        #pragma unroll 8
        for (int idx = t; idx < LL; idx += 256) {
            gr[idx] = sre[IDX(idx)];
            gi[idx] = sim[IDX(idx)];
        }
    }
}

// ---------------------------------------------------------------------------
// K3: y = x2cat @ [C_real^T ; -C_imag^T] + u * D
// grid (L/128, B), 512 threads, out tile 128(l) x 128(h), K = 2P = 128
// Register tile 4(l) x 8(h).
// ---------------------------------------------------------------------------
__global__ __launch_bounds__(512) void k_out(const float* __restrict__ u,
                                             const float* __restrict__ Cr,
                                             const float* __restrict__ Ci,
                                             const float* __restrict__ Dv,
                                             float* __restrict__ out)
{
    extern __shared__ float sm[];
    float* Ask = sm;               // [pc][l] stride 128 (matches g_buf layout)
    float* Wsk = sm + 128 * 128;   // [pc][h] stride 132
    const int b = blockIdx.y, l0 = blockIdx.x * 128, tid = threadIdx.x;

    #pragma unroll 4
    for (int idx = tid; idx < 128 * 32; idx += 512) {
        int pc = idx >> 5, lq = idx & 31;   // float4 granularity over l
        const float4* src = (const float4*)(g_buf + ((size_t)(b * 128 + pc)) * LL + l0);
        ((float4*)(Ask + pc * 128))[lq] = src[lq];
    }
    #pragma unroll 4
    for (int idx = tid; idx < 128 * 64; idx += 512) {
        int h = idx >> 6, p = idx & 63;
        Wsk[p * 132 + h]        = Cr[h * 64 + p];
        Wsk[(64 + p) * 132 + h] = -Ci[h * 64 + p];
    }
    __syncthreads();

    const int tx = tid & 15, ty = tid >> 4;   // tx -> h (8), ty(0..31) -> l (4)
    float acc[4][8];   // [l-idx][h-idx]
    #pragma unroll
    for (int i = 0; i < 4; i++)
        #pragma unroll
        for (int j = 0; j < 8; j++) acc[i][j] = 0.f;

    #pragma unroll 4
    for (int k = 0; k < 128; k++) {
        float4 a0 = *(const float4*)(Ask + k * 128 + (ty << 2));
        float4 w0 = *(const float4*)(Wsk + k * 132 + (tx << 2));
        float4 w1 = *(const float4*)(Wsk + k * 132 + 64 + (tx << 2));
        float av[4] = {a0.x, a0.y, a0.z, a0.w};
        float wv[8] = {w0.x, w0.y, w0.z, w0.w, w1.x, w1.y, w1.z, w1.w};
        #pragma unroll
        for (int i = 0; i < 4; i++)
            #pragma unroll
            for (int j = 0; j < 8; j++)
                acc[i][j] = fmaf(av[i], wv[j], acc[i][j]);
    }

    float d0[4], d1[4];
    #pragma unroll
    for (int j = 0; j < 4; j++) {
        d0[j] = Dv[tx * 4 + j];
        d1[j] = Dv[64 + tx * 4 + j];
    }

    #pragma unroll
    for (int li = 0; li < 4; li++) {
        int l = ty * 4 + li;
        const float* urow = u + ((size_t)b * LL + l0 + l) * HH;
        float*       orow = out + ((size_t)b * LL + l0 + l) * HH;
        float4 u0 = *(const float4*)(urow + (tx << 2));
        float4 u1 = *(const float4*)(urow + 64 + (tx << 2));
        float4 o0, o1;
        o0.x = fmaf(u0.x, d0[0], acc[li][0]);
        o0.y = fmaf(u0.y, d0[1], acc[li][1]);
        o0.z = fmaf(u0.z, d0[2], acc[li][2]);
        o0.w = fmaf(u0.w, d0[3], acc[li][3]);
        o1.x = fmaf(u1.x, d1[0], acc[li][4]);
        o1.y = fmaf(u1.y, d1[1], acc[li][5]);
        o1.z = fmaf(u1.z, d1[2], acc[li][6]);
        o1.w = fmaf(u1.w, d1[3], acc[li][7]);
        *(float4*)(orow + (tx << 2))      = o0;
        *(float4*)(orow + 64 + (tx << 2)) = o1;
    }
}

// ---------------------------------------------------------------------------
extern "C" void kernel_launch(void* const* d_in, const int* in_sizes, int n_in,
                              void* d_out, int out_size)
{
    const float* u  = (const float*)d_in[0];   // (B,L,H)
    const float* Ad = (const float*)d_in[1];   // (P)
    const float* Br = (const float*)d_in[2];   // (P,H)
    const float* Bi = (const float*)d_in[3];   // (P,H)
    const float* Cr = (const float*)d_in[4];   // (H,P)
    const float* Ci = (const float*)d_in[5];   // (H,P)
    const float* Dv = (const float*)d_in[6];   // (H)
    const float* st = (const float*)d_in[7];   // (P)
    float* out = (float*)d_out;                // (B,L,H)

    const int smem_bu   = 2 * 128 * 132 * (int)sizeof(float);            // 135168
    const int smem_scan = (2 * LLP + 64) * (int)sizeof(float);           // 67840
    const int smem_out  = (128 * 128 + 128 * 132) * (int)sizeof(float);  // 133120

    cudaFuncSetAttribute(k_bu,   cudaFuncAttributeMaxDynamicSharedMemorySize, smem_bu);
    cudaFuncSetAttribute(k_scan, cudaFuncAttributeMaxDynamicSharedMemorySize, smem_scan);
    cudaFuncSetAttribute(k_out,  cudaFuncAttributeMaxDynamicSharedMemorySize, smem_out);

    k_bu  <<<dim3(LL / 128, BB), 512, smem_bu  >>>(u, Br, Bi);
    k_scan<<<dim3(PP,       BB), 256, smem_scan>>>(Ad, st);
    k_out <<<dim3(LL / 128, BB), 512, smem_out >>>(u, Cr, Ci, Dv, out);
}